// round 14
// baseline (speedup 1.0000x reference)
#include <cuda_runtime.h>
#include <cuda_bf16.h>
#include <cstdint>

// ---------------------------------------------------------------------------
// Transformer forward (B=16,T=512,V=2048,D=512,HD=64,NH=8,L=6,F=2048,MD=16)
// Round 14: R13 + plane-major MMA ordering (break accumulator RAW chains),
// causal block-skip in scores GEMM, widened valbias.
// ---------------------------------------------------------------------------

#define Bsz 16
#define Tq  512
#define Dm  512
#define HDm 64
#define NHm 8
#define Lm  6
#define Fm  2048
#define Vm  2048
#define ROWS (Bsz*Tq)   // 8192
#define QKVN 192

typedef __nv_bfloat16 bf16;

// fp32 buffers
__device__ float d_h   [ROWS * Dm];
__device__ float d_qkv [ROWS * QKVN];
__device__ float d_att [Bsz * Tq * Tq];
__device__ float d_attA[ROWS * 17];
__device__ float d_vals[2 * ROWS * HDm];      // 2 split-K partials
// bf16 hi/lo planes: [0,N) = hi, [N,2N) = lo
__device__ bf16 d_y2   [2 * ROWS * Dm];
__device__ bf16 d_qkv2 [2 * ROWS * QKVN];
__device__ bf16 d_vt2  [2 * Bsz * HDm * Tq];
__device__ bf16 d_att2 [2 * Bsz * Tq * Tq];
__device__ bf16 d_vals2[2 * ROWS * HDm];
__device__ bf16 d_ffn2 [2 * ROWS * Fm];
__device__ bf16 d_h2   [2 * ROWS * Dm];
// transposed+split weights [N][K] planes
__device__ bf16 d_wqkvt[2 * Lm * QKVN * Dm];
__device__ bf16 d_wost [2 * Lm * Dm * HDm];
__device__ bf16 d_w1t  [2 * Lm * Fm * Dm];
__device__ bf16 d_w2t  [2 * Lm * Dm * Fm];
__device__ bf16 d_wot  [2 * Vm * Dm];
__device__ float d_bqkv[Lm * QKVN];

// ---------------------------------------------------------------------------
__device__ __forceinline__ void cp16(void* s, const void* g) {
    uint32_t sa = (uint32_t)__cvta_generic_to_shared(s);
    asm volatile("cp.async.cg.shared.global [%0], [%1], 16;" :: "r"(sa), "l"(g));
}
__device__ __forceinline__ void cp_commit() {
    asm volatile("cp.async.commit_group;");
}
__device__ __forceinline__ void bfsplit(float v, bf16& h, bf16& l) {
    h = __float2bfloat16(v);
    l = __float2bfloat16(v - __bfloat162float(h));
}
__device__ __forceinline__ void mma_bf16(float* d, const uint32_t* a, const uint32_t* b) {
    asm volatile(
        "mma.sync.aligned.m16n8k16.row.col.f32.bf16.bf16.f32 "
        "{%0,%1,%2,%3}, {%4,%5,%6,%7}, {%8,%9}, {%0,%1,%2,%3};"
        : "+f"(d[0]), "+f"(d[1]), "+f"(d[2]), "+f"(d[3])
        : "r"(a[0]), "r"(a[1]), "r"(a[2]), "r"(a[3]), "r"(b[0]), "r"(b[1]));
}
__device__ __forceinline__ void ldsm_x4(uint32_t& r0, uint32_t& r1,
                                        uint32_t& r2, uint32_t& r3, uint32_t addr) {
    asm volatile("ldmatrix.sync.aligned.m8n8.x4.shared.b16 {%0,%1,%2,%3}, [%4];"
                 : "=r"(r0), "=r"(r1), "=r"(r2), "=r"(r3) : "r"(addr));
}

// ---------------------------------------------------------------------------
// bgemm: bf16x3 GEMM, ldmatrix loads, plane-major MMA order, 2 CTAs/SM.
//   C[M,N] (+)= (Ah+Al)[M,K] @ (Bh+Bl)^T, B planes stored [N][K].
//   BM=128, BK=32, BN in {64,128}. 256 threads. CAUSAL: skip col0>row0+127.
// ---------------------------------------------------------------------------
template<int BN_, bool ADD, bool RELU, bool CAUSAL>
__global__ __launch_bounds__(256, 2) void bgemm(
    const bf16* __restrict__ Ah, const bf16* __restrict__ Al,
    const bf16* __restrict__ Bh, const bf16* __restrict__ Bl,
    const float* __restrict__ bias,
    float* __restrict__ Cf, bf16* __restrict__ Ch, bf16* __restrict__ Cl,
    int K, int lda, int ldb, int ldc,
    long sA, long sB, long sC,
    int splitk, long sKout)
{
    constexpr int NWN = BN_ / 32;                 // 4 or 2
    constexpr int WM  = (NWN == 4) ? 64 : 32;
    constexpr int MT  = WM / 16;
    constexpr int AW  = 20;                        // words per smem row
    constexpr int APL = 128 * AW;
    constexpr int BPL = BN_ * AW;

    extern __shared__ uint32_t smw[];

    const int ks = blockIdx.x % splitk;
    const int colblk = blockIdx.x / splitk;
    const int Kl = K / splitk;

    const int row0 = blockIdx.y * 128;
    const int col0 = colblk * BN_;
    if (CAUSAL && col0 > row0 + 127) return;      // never read past diagonal

    Ah += (long)blockIdx.z * sA + (long)ks * Kl;
    Al += (long)blockIdx.z * sA + (long)ks * Kl;
    Bh += (long)blockIdx.z * sB + (long)ks * Kl;
    Bl += (long)blockIdx.z * sB + (long)ks * Kl;
    long cofs = (long)blockIdx.z * sC + (long)ks * sKout;
    if (Cf) Cf += cofs;
    if (Ch) { Ch += cofs; Cl += cofs; }

    const int tid = threadIdx.x, lane = tid & 31, wid = tid >> 5;
    const int wn = wid % NWN, wm = wid / NWN;
    const int g = lane >> 2, tq = lane & 3;

    float acc[MT][4][4];
    #pragma unroll
    for (int mt = 0; mt < MT; mt++)
        #pragma unroll
        for (int nt = 0; nt < 4; nt++)
            #pragma unroll
            for (int i = 0; i < 4; i++) acc[mt][nt][i] = 0.f;

    auto copyA = [&](int kc, int buf) {
        int r = tid >> 1, half = tid & 1;
        long go = (long)(row0 + r) * lda + kc * 32 + half * 16;
        uint32_t* da = smw + (buf * 2 + 0) * APL + r * AW + half * 8;
        uint32_t* db = smw + (buf * 2 + 1) * APL + r * AW + half * 8;
        cp16(da,     Ah + go);
        cp16(da + 4, Ah + go + 8);
        cp16(db,     Al + go);
        cp16(db + 4, Al + go + 8);
    };
    auto copyB = [&](int kc, int buf) {
        uint32_t* b0 = smw + 4 * APL + (buf * 2 + 0) * BPL;
        uint32_t* b1 = smw + 4 * APL + (buf * 2 + 1) * BPL;
        if (BN_ == 128) {
            int r = tid >> 1, half = tid & 1;
            long go = (long)(col0 + r) * ldb + kc * 32 + half * 16;
            cp16(b0 + r * AW + half * 8,     Bh + go);
            cp16(b0 + r * AW + half * 8 + 4, Bh + go + 8);
            cp16(b1 + r * AW + half * 8,     Bl + go);
            cp16(b1 + r * AW + half * 8 + 4, Bl + go + 8);
        } else {
            int r = tid >> 2, c = tid & 3;
            long go = (long)(col0 + r) * ldb + kc * 32 + c * 8;
            cp16(b0 + r * AW + c * 4, Bh + go);
            cp16(b1 + r * AW + c * 4, Bl + go);
        }
    };

    const uint32_t smbase = (uint32_t)__cvta_generic_to_shared(smw);
    const uint32_t a_off = (uint32_t)((wm * WM + (lane & 15)) * AW * 4
                                      + ((lane >> 4) & 1) * 16);
    const uint32_t b_off = (uint32_t)((wn * 32 + (lane & 7) + ((lane >> 4) & 1) * 8) * AW * 4
                                      + ((lane >> 3) & 1) * 16);

    const int nk = Kl / 32;
    copyA(0, 0); copyB(0, 0);
    cp_commit();

    int buf = 0;
    for (int kc = 0; kc < nk; kc++) {
        if (kc + 1 < nk) {
            copyA(kc + 1, buf ^ 1); copyB(kc + 1, buf ^ 1);
            cp_commit();
            asm volatile("cp.async.wait_group 1;");
        } else {
            asm volatile("cp.async.wait_group 0;");
        }
        __syncthreads();

        const uint32_t aBh = smbase + (buf * 2 + 0) * APL * 4 + a_off;
        const uint32_t aBl = aBh + APL * 4;
        const uint32_t bBh = smbase + (4 * APL + (buf * 2 + 0) * BPL) * 4 + b_off;
        const uint32_t bBl = bBh + BPL * 4;

        #pragma unroll
        for (int kk = 0; kk < 2; kk++) {          // two k16 sub-steps
            const uint32_t kb = kk * 32;           // byte offset
            uint32_t ah[MT][4], al[MT][4];
            #pragma unroll
            for (int mt = 0; mt < MT; mt++) {
                ldsm_x4(ah[mt][0], ah[mt][1], ah[mt][2], ah[mt][3],
                        aBh + mt * (16 * AW * 4) + kb);
                ldsm_x4(al[mt][0], al[mt][1], al[mt][2], al[mt][3],
                        aBl + mt * (16 * AW * 4) + kb);
            }
            uint32_t bh[4][2], bl[4][2];
            #pragma unroll
            for (int np = 0; np < 2; np++) {
                ldsm_x4(bh[np * 2][0], bh[np * 2][1], bh[np * 2 + 1][0], bh[np * 2 + 1][1],
                        bBh + np * (16 * AW * 4) + kb);
                ldsm_x4(bl[np * 2][0], bl[np * 2][1], bl[np * 2 + 1][0], bl[np * 2 + 1][1],
                        bBl + np * (16 * AW * 4) + kb);
            }
            // plane-major: 3 passes over all (mt,nt) -> accumulator-reuse
            // distance of MT*4 instructions instead of 1 (hides MMA latency)
            #pragma unroll
            for (int mt = 0; mt < MT; mt++)
                #pragma unroll
                for (int nt = 0; nt < 4; nt++)
                    mma_bf16(acc[mt][nt], ah[mt], bl[nt]);
            #pragma unroll
            for (int mt = 0; mt < MT; mt++)
                #pragma unroll
                for (int nt = 0; nt < 4; nt++)
                    mma_bf16(acc[mt][nt], al[mt], bh[nt]);
            #pragma unroll
            for (int mt = 0; mt < MT; mt++)
                #pragma unroll
                for (int nt = 0; nt < 4; nt++)
                    mma_bf16(acc[mt][nt], ah[mt], bh[nt]);
        }
        __syncthreads();
        buf ^= 1;
    }

    #pragma unroll
    for (int mt = 0; mt < MT; mt++) {
        int r0 = row0 + wm * WM + mt * 16 + g;
        #pragma unroll
        for (int nt = 0; nt < 4; nt++) {
            int c0 = col0 + wn * 32 + nt * 8 + tq * 2;
            #pragma unroll
            for (int i = 0; i < 2; i++) {
                #pragma unroll
                for (int j = 0; j < 2; j++) {
                    float v = acc[mt][nt][i * 2 + j];
                    int r = r0 + i * 8, c = c0 + j;
                    if (bias) v += bias[c];
                    if (RELU) v = fmaxf(v, 0.f);
                    long o = (long)r * ldc + c;
                    if (ADD) v += Cf[o];
                    if (Cf) Cf[o] = v;
                    if (Ch) {
                        bf16 hh, ll; bfsplit(v, hh, ll);
                        Ch[o] = hh; Cl[o] = ll;
                    }
                }
            }
        }
    }
}

// ---------------------------------------------------------------------------
// small kernels
// ---------------------------------------------------------------------------
__global__ void embed_kernel(const int* __restrict__ idx,
                             const float* __restrict__ emb,
                             float* __restrict__ h)
{
    int i = blockIdx.x * blockDim.x + threadIdx.x;
    int d = i & (Dm - 1);
    int row = i >> 9;
    int t = row & (Tq - 1);
    int tok = idx[row];
    float x = emb[(long)tok * Dm + d];
    int m = d >> 1;
    float inv = __expf(-(float)m * (9.210340371976184f / 128.0f));
    float ang = (float)t * inv;
    float pe = (d & 1) ? cosf(ang) : sinf(ang);
    h[i] = 2.f * x + pe;
}

__global__ void split_kernel(const float* __restrict__ src,
                             bf16* __restrict__ hi, bf16* __restrict__ lo, int n)
{
    int i = blockIdx.x * blockDim.x + threadIdx.x;
    if (i >= n) return;
    bf16 h, l; bfsplit(src[i], h, l);
    hi[i] = h; lo[i] = l;
}

// fused QKV prep: gather Wq|Wk|Wv, transpose to [n][k], split planes; + bias
__global__ void qkvprep_kernel(
    const float* __restrict__ Wq, const float* __restrict__ Wk,
    const float* __restrict__ Wv,
    const float* __restrict__ bq, const float* __restrict__ bk,
    const float* __restrict__ bv,
    bf16* __restrict__ oh, bf16* __restrict__ ol, float* __restrict__ bqkv)
{
    __shared__ float t[32][33];
    int l = blockIdx.z;
    int n0 = blockIdx.x * 32, k0 = blockIdx.y * 32;
    int x = threadIdx.x;
    for (int y = threadIdx.y; y < 32; y += 8) {
        int n = n0 + x, k = k0 + y;
        float v;
        if (n < 64)       v = Wq[((long)l * Dm + k) * HDm + n];
        else if (n < 128) v = Wk[((long)l * Dm + k) * HDm + n - 64];
        else              v = Wv[((long)l * Dm + k) * HDm + n - 128];
        t[y][x] = v;
    }
    if (blockIdx.y == 0 && threadIdx.y == 0) {
        int n = n0 + x;
        float bv_;
        if (n < 64)       bv_ = bq[l * HDm + n];
        else if (n < 128) bv_ = bk[l * HDm + n - 64];
        else              bv_ = bv[l * HDm + n - 128];
        bqkv[l * QKVN + n] = bv_;
    }
    __syncthreads();
    for (int y = threadIdx.y; y < 32; y += 8) {
        bf16 h, lo2; bfsplit(t[x][y], h, lo2);
        long o = (long)l * QKVN * Dm + (long)(n0 + y) * Dm + k0 + x;
        oh[o] = h; ol[o] = lo2;
    }
}

// tiled transpose + split: in fp32 [R][C] -> out planes bf16 [C][R]
__global__ void tsplit_kernel(const float* __restrict__ in,
                              bf16* __restrict__ oh, bf16* __restrict__ ol,
                              int R, int C, long sIn, long sOut)
{
    __shared__ float t[32][33];
    int z = blockIdx.z;
    in += z * sIn; oh += z * sOut; ol += z * sOut;
    int c0 = blockIdx.x * 32, r0 = blockIdx.y * 32;
    int x = threadIdx.x;
    for (int y = threadIdx.y; y < 32; y += 8)
        t[y][x] = in[(long)(r0 + y) * C + c0 + x];
    __syncthreads();
    for (int y = threadIdx.y; y < 32; y += 8) {
        bf16 h, l; bfsplit(t[x][y], h, l);
        long o = (long)(c0 + y) * R + r0 + x;
        oh[o] = h; ol[o] = l;
    }
}

// WoSum transposed: wost[l][d][h] = sum_n Wo[l][n*64+h][d], split planes
__global__ void wost_kernel(const float* __restrict__ Wo, bf16* __restrict__ wh,
                            bf16* __restrict__ wl)
{
    int i = blockIdx.x * blockDim.x + threadIdx.x;
    if (i >= Lm * Dm * HDm) return;
    int h = i & (HDm - 1);
    int d = (i >> 6) & (Dm - 1);
    int l = i >> 15;
    float s = 0.f;
    #pragma unroll
    for (int n = 0; n < NHm; n++)
        s += Wo[((long)l * (NHm * HDm) + n * HDm + h) * Dm + d];
    bf16 hh, ll; bfsplit(s, hh, ll);
    wh[i] = hh; wl[i] = ll;
}

// LayerNorm -> bf16 hi/lo planes
__global__ __launch_bounds__(256) void ln_kernel(
    const float* __restrict__ x, const float* __restrict__ g,
    const float* __restrict__ be, bf16* __restrict__ yh, bf16* __restrict__ yl)
{
    long base = (long)blockIdx.x * Dm;
    int tid = threadIdx.x;
    float v0 = x[base + tid], v1 = x[base + tid + 256];
    float s = v0 + v1;
    float ss = v0 * v0 + v1 * v1;
    __shared__ float rs[8], rss[8], mv[2];
    int lane = tid & 31, warp = tid >> 5;
    #pragma unroll
    for (int off = 16; off; off >>= 1) {
        s  += __shfl_xor_sync(0xffffffffu, s, off);
        ss += __shfl_xor_sync(0xffffffffu, ss, off);
    }
    if (lane == 0) { rs[warp] = s; rss[warp] = ss; }
    __syncthreads();
    if (tid == 0) {
        float S = 0.f, SS = 0.f;
        #pragma unroll
        for (int w = 0; w < 8; w++) { S += rs[w]; SS += rss[w]; }
        float mean = S * (1.f / Dm);
        float var  = SS * (1.f / Dm) - mean * mean;
        mv[0] = mean; mv[1] = rsqrtf(var + 1e-5f);
    }
    __syncthreads();
    float mean = mv[0], inv = mv[1];
    float y0 = (v0 - mean) * inv * g[tid]       + be[tid];
    float y1 = (v1 - mean) * inv * g[tid + 256] + be[tid + 256];
    bf16 h0, l0, h1, l1;
    bfsplit(y0, h0, l0); bfsplit(y1, h1, l1);
    yh[base + tid] = h0;       yl[base + tid] = l0;
    yh[base + tid + 256] = h1; yl[base + tid + 256] = l1;
}

// V transpose from qkv fp32 (cols 128..191) -> vt planes [b][h][s]
__global__ void vt_kernel(const float* __restrict__ qkv,
                          bf16* __restrict__ vh, bf16* __restrict__ vl)
{
    __shared__ float tile[32][33];
    int b = blockIdx.z;
    int s0 = blockIdx.x * 32, h0 = blockIdx.y * 32;
    int x = threadIdx.x;
    for (int y = threadIdx.y; y < 32; y += 8)
        tile[y][x] = qkv[((long)(b * Tq + s0 + y)) * QKVN + 128 + h0 + x];
    __syncthreads();
    for (int y = threadIdx.y; y < 32; y += 8) {
        bf16 hh, ll; bfsplit(tile[x][y], hh, ll);
        long o = ((long)b * HDm + h0 + y) * Tq + s0 + x;
        vh[o] = hh; vl[o] = ll;
    }
}

// softmax + rel-bias + buckets
__global__ __launch_bounds__(256) void softmax_kernel(
    const float* __restrict__ qkv, const float* __restrict__ att,
    const float* __restrict__ tbl,
    bf16* __restrict__ ah_, bf16* __restrict__ al_, float* __restrict__ attA)
{
    const int row = blockIdx.x;
    const int b = row >> 9, t = row & (Tq - 1);
    const int tid = threadIdx.x, lane = tid & 31, warp = tid >> 5;

    __shared__ float qs[HDm];
    __shared__ float qrel[17];
    __shared__ float srow[Tq];
    __shared__ float red[8];

    if (tid < HDm) qs[tid] = qkv[(long)row * QKVN + tid];
    __syncthreads();
    if (tid < 17) {
        const float* tb = tbl + tid * HDm;
        float s = 0.f;
        #pragma unroll
        for (int hh = 0; hh < HDm; hh++) s += qs[hh] * tb[hh];
        qrel[tid] = s;
    }
    __syncthreads();

    const float scale = 0.125f;
    const float* arow = att + ((long)b * Tq + t) * Tq;
    for (int s = tid; s <= t; s += 256) {
        int dm = s - t + 16; if (dm < 0) dm = 0;
        srow[s] = (arow[s] + qrel[dm]) * scale;
    }
    __syncthreads();

    float m = -1e30f;
    for (int s = tid; s <= t; s += 256) m = fmaxf(m, srow[s]);
    #pragma unroll
    for (int off = 16; off; off >>= 1)
        m = fmaxf(m, __shfl_xor_sync(0xffffffffu, m, off));
    if (lane == 0) red[warp] = m;
    __syncthreads();
    if (tid == 0) {
        float mm = red[0];
        #pragma unroll
        for (int w = 1; w < 8; w++) mm = fmaxf(mm, red[w]);
        red[0] = mm;
    }
    __syncthreads();
    m = red[0];
    __syncthreads();

    float sum = 0.f;
    for (int s = tid; s < Tq; s += 256) {
        float e = (s <= t) ? __expf(srow[s] - m) : 0.f;
        srow[s] = e;
        sum += e;
    }
    #pragma unroll
    for (int off = 16; off; off >>= 1)
        sum += __shfl_xor_sync(0xffffffffu, sum, off);
    if (lane == 0) red[warp] = sum;
    __syncthreads();
    if (tid == 0) {
        float ss = 0.f;
        #pragma unroll
        for (int w = 0; w < 8; w++) ss += red[w];
        red[0] = ss;
    }
    __syncthreads();
    float inv = 1.f / red[0];
    __syncthreads();

    bf16* ph = ah_ + ((long)b * Tq + t) * Tq;
    bf16* pl = al_ + ((long)b * Tq + t) * Tq;
    for (int s = tid; s < Tq; s += 256) {
        bf16 hh, ll; bfsplit(srow[s] * inv, hh, ll);
        ph[s] = hh; pl[s] = ll;
    }

    float a0 = 0.f;
    for (int s = tid; s < Tq; s += 256)
        if (s <= t - 16) a0 += srow[s];
    #pragma unroll
    for (int off = 16; off; off >>= 1)
        a0 += __shfl_xor_sync(0xffffffffu, a0, off);
    if (lane == 0) red[warp] = a0;
    __syncthreads();
    if (tid == 0) {
        float ss = 0.f;
        #pragma unroll
        for (int w = 0; w < 8; w++) ss += red[w];
        attA[(long)row * 17 + 0] = ss * inv;
    }
    if (tid >= 1 && tid <= 16) {
        int s = t - 16 + tid;
        attA[(long)row * 17 + tid] = (s >= 0) ? srow[s] * inv : 0.f;
    }
}

// vals = partial0 + partial1 + attA @ tbl[0:17]; 4 rows per block
__global__ __launch_bounds__(256) void valbias_kernel(
    const float* __restrict__ vals, const float* __restrict__ attA,
    const float* __restrict__ tbl,
    bf16* __restrict__ vh, bf16* __restrict__ vl)
{
    int r4 = threadIdx.x >> 6;                  // row within block group
    int hh = threadIdx.x & 63;
    int row = blockIdx.x * 4 + r4;
    __shared__ float aa[4][17];
    if (hh < 17) aa[r4][hh] = attA[(long)row * 17 + hh];
    __syncthreads();
    long o = (long)row * HDm + hh;
    float v = vals[o] + vals[(long)ROWS * HDm + o];
    #pragma unroll
    for (int j = 0; j < 17; j++) v += aa[r4][j] * tbl[j * HDm + hh];
    bf16 h, l; bfsplit(v, h, l);
    vh[o] = h;
    vl[o] = l;
}

// ---------------------------------------------------------------------------
extern "C" void kernel_launch(void* const* d_in, const int* in_sizes, int n_in,
                              void* d_out, int out_size)
{
    const int*   idx  = (const int*)  d_in[0];
    const float* emb  = (const float*)d_in[1];
    const float* Wq   = (const float*)d_in[2];
    const float* bq   = (const float*)d_in[3];
    const float* Wk   = (const float*)d_in[4];
    const float* bk   = (const float*)d_in[5];
    const float* Wv   = (const float*)d_in[6];
    const float* bv   = (const float*)d_in[7];
    const float* rel  = (const float*)d_in[8];
    const float* Wo   = (const float*)d_in[9];
    const float* bo   = (const float*)d_in[10];
    const float* g1   = (const float*)d_in[11];
    const float* be1  = (const float*)d_in[12];
    const float* g2   = (const float*)d_in[13];
    const float* be2  = (const float*)d_in[14];
    const float* W1   = (const float*)d_in[15];
    const float* b1   = (const float*)d_in[16];
    const float* W2   = (const float*)d_in[17];
    const float* b2   = (const float*)d_in[18];
    const float* Wout = (const float*)d_in[19];
    const float* bout = (const float*)d_in[20];
    float* out = (float*)d_out;

    float *h, *qkv, *att, *attA, *vals, *bqkv;
    bf16 *y2, *qkv2, *vt2, *att2, *vals2, *ffn2, *h2;
    bf16 *wqkvt, *wost, *w1t, *w2t, *wot;
    cudaGetSymbolAddress((void**)&h,     d_h);
    cudaGetSymbolAddress((void**)&qkv,   d_qkv);
    cudaGetSymbolAddress((void**)&att,   d_att);
    cudaGetSymbolAddress((void**)&attA,  d_attA);
    cudaGetSymbolAddress((void**)&vals,  d_vals);
    cudaGetSymbolAddress((void**)&bqkv,  d_bqkv);
    cudaGetSymbolAddress((void**)&y2,    d_y2);
    cudaGetSymbolAddress((void**)&qkv2,  d_qkv2);
    cudaGetSymbolAddress((void**)&vt2,   d_vt2);
    cudaGetSymbolAddress((void**)&att2,  d_att2);
    cudaGetSymbolAddress((void**)&vals2, d_vals2);
    cudaGetSymbolAddress((void**)&ffn2,  d_ffn2);
    cudaGetSymbolAddress((void**)&h2,    d_h2);
    cudaGetSymbolAddress((void**)&wqkvt, d_wqkvt);
    cudaGetSymbolAddress((void**)&wost,  d_wost);
    cudaGetSymbolAddress((void**)&w1t,   d_w1t);
    cudaGetSymbolAddress((void**)&w2t,   d_w2t);
    cudaGetSymbolAddress((void**)&wot,   d_wot);

    const int SM128 = (4 * 2560 + 4 * 128 * 20) * 4;   // 81920 B
    const int SM64  = (4 * 2560 + 4 *  64 * 20) * 4;   // 61440 B
    cudaFuncSetAttribute(bgemm<128, false, false, false>, cudaFuncAttributeMaxDynamicSharedMemorySize, SM128);
    cudaFuncSetAttribute(bgemm<128, false, false, true >, cudaFuncAttributeMaxDynamicSharedMemorySize, SM128);
    cudaFuncSetAttribute(bgemm<128, true,  false, false>, cudaFuncAttributeMaxDynamicSharedMemorySize, SM128);
    cudaFuncSetAttribute(bgemm<128, false, true , false>, cudaFuncAttributeMaxDynamicSharedMemorySize, SM128);
    cudaFuncSetAttribute(bgemm<64,  false, false, false>, cudaFuncAttributeMaxDynamicSharedMemorySize, SM64);

    const long PY   = (long)ROWS * Dm;
    const long PQKV = (long)ROWS * QKVN;
    const long PVT  = (long)Bsz * HDm * Tq;
    const long PATT = (long)Bsz * Tq * Tq;
    const long PVAL = (long)ROWS * HDm;
    const long PFFN = (long)ROWS * Fm;
    const long PWQ  = (long)Lm * QKVN * Dm;
    const long PWS  = (long)Lm * Dm * HDm;
    const long PW1  = (long)Lm * Fm * Dm;
    const long PW2  = (long)Lm * Dm * Fm;
    const long PWO  = (long)Vm * Dm;

    // ---- prep (minimal before first GEMM so ncu's launch #3 is bgemm) ----
    embed_kernel<<<ROWS * Dm / 256, 256>>>(idx, emb, h);                    // #0
    qkvprep_kernel<<<dim3(QKVN / 32, Dm / 32, Lm), dim3(32, 8)>>>(
        Wq, Wk, Wv, bq, bk, bv, wqkvt, wqkvt + PWQ, bqkv);                  // #1

    for (int l = 0; l < Lm; l++) {
        const float* tbl = rel + (long)l * 33 * HDm;

        ln_kernel<<<ROWS, 256>>>(h, g1 + l * Dm, be1 + l * Dm, y2, y2 + PY);  // #2 (l=0)

        // QKV: [8192,512] x [512,192]                                         // #3 (l=0)
        {
            dim3 grid(QKVN / 64, ROWS / 128, 1);
            bgemm<64, false, false, false><<<grid, 256, SM64>>>(
                y2, y2 + PY,
                wqkvt + (long)l * QKVN * Dm, wqkvt + PWQ + (long)l * QKVN * Dm,
                bqkv + l * QKVN,
                qkv, qkv2, qkv2 + PQKV,
                Dm, Dm, Dm, QKVN, 0, 0, 0, 1, 0);
        }

        if (l == 0) {
            wost_kernel<<<(int)((PWS + 255) / 256), 256>>>(Wo, wost, wost + PWS);
            tsplit_kernel<<<dim3(Fm / 32, Dm / 32, Lm), dim3(32, 8)>>>(
                W1, w1t, w1t + PW1, Dm, Fm, (long)Dm * Fm, (long)Fm * Dm);
            tsplit_kernel<<<dim3(Dm / 32, Fm / 32, Lm), dim3(32, 8)>>>(
                W2, w2t, w2t + PW2, Fm, Dm, (long)Fm * Dm, (long)Dm * Fm);
            tsplit_kernel<<<dim3(Vm / 32, Dm / 32, 1), dim3(32, 8)>>>(
                Wout, wot, wot + PWO, Dm, Vm, 0, 0);
        }

        // V transpose -> vt planes
        {
            dim3 grid(Tq / 32, HDm / 32, Bsz);
            vt_kernel<<<grid, dim3(32, 8)>>>(qkv, vt2, vt2 + PVT);
        }

        // scores = Q @ K^T (causal: skip upper-triangle blocks)
        {
            dim3 grid(Tq / 128, Tq / 128, Bsz);
            bgemm<128, false, false, true><<<grid, 256, SM128>>>(
                qkv2, qkv2 + PQKV,
                qkv2 + 64, qkv2 + PQKV + 64,
                nullptr, att, nullptr, nullptr,
                HDm, QKVN, QKVN, Tq,
                (long)Tq * QKVN, (long)Tq * QKVN, (long)Tq * Tq, 1, 0);
        }

        softmax_kernel<<<ROWS, 256>>>(qkv, att, tbl, att2, att2 + PATT, attA);

        // vals = att @ V (split-K=2)
        {
            dim3 grid(2, Tq / 128, Bsz);
            bgemm<64, false, false, false><<<grid, 256, SM64>>>(
                att2, att2 + PATT,
                vt2, vt2 + PVT,
                nullptr, vals, nullptr, nullptr,
                Tq, Tq, Tq, HDm,
                (long)Tq * Tq, (long)HDm * Tq, (long)Tq * HDm, 2, PVAL);
        }

        valbias_kernel<<<ROWS / 4, 256>>>(vals, attA, tbl, vals2, vals2 + PVAL);

        // h += vals @ WoSum + bo
        {
            dim3 grid(Dm / 128, ROWS / 128, 1);
            bgemm<128, true, false, false><<<grid, 256, SM128>>>(
                vals2, vals2 + PVAL,
                wost + (long)l * Dm * HDm, wost + PWS + (long)l * Dm * HDm,
                bo + l * Dm,
                h, nullptr, nullptr,
                HDm, HDm, HDm, Dm, 0, 0, 0, 1, 0);
        }

        ln_kernel<<<ROWS, 256>>>(h, g2 + l * Dm, be2 + l * Dm, y2, y2 + PY);

        // ffn = relu(y @ W1 + b1)
        {
            dim3 grid(Fm / 128, ROWS / 128, 1);
            bgemm<128, false, true, false><<<grid, 256, SM128>>>(
                y2, y2 + PY,
                w1t + (long)l * Fm * Dm, w1t + PW1 + (long)l * Fm * Dm,
                b1 + l * Fm,
                nullptr, ffn2, ffn2 + PFFN,
                Dm, Dm, Dm, Fm, 0, 0, 0, 1, 0);
        }

        // h += ffn @ W2 + b2
        {
            dim3 grid(Dm / 128, ROWS / 128, 1);
            bgemm<128, true, false, false><<<grid, 256, SM128>>>(
                ffn2, ffn2 + PFFN,
                w2t + (long)l * Dm * Fm, w2t + PW2 + (long)l * Dm * Fm,
                b2 + l * Dm,
                h, nullptr, nullptr,
                Fm, Fm, Fm, Dm, 0, 0, 0, 1, 0);
        }
    }

    // logits = h @ Wout + bout
    split_kernel<<<(int)((PY + 255) / 256), 256>>>(h, h2, h2 + PY, (int)PY);
    {
        dim3 grid(Vm / 128, ROWS / 128, 1);
        bgemm<128, false, false, false><<<grid, 256, SM128>>>(
            h2, h2 + PY,
            wot, wot + PWO,
            bout, out, nullptr, nullptr,
            Dm, Dm, Dm, Vm, 0, 0, 0, 1, 0);
    }
}